// round 15
// baseline (speedup 1.0000x reference)
#include <cuda_runtime.h>
#include <cuda_bf16.h>
#include <math.h>
#include <stdint.h>

// ---------------- problem constants ----------------
#define CC   192
#define SS   4
#define NH   6
#define HD   32
#define NT   64
#define BWIN 2048
#define TOK  131072
#define C3   576
#define C4   768

#define PA   200   // A smem pitch (bf16 elems)
#define PB   72    // pitch for 64-col chunks
#define PB2  200   // pitch for 192-col chunks (fc2 B)

#define AB   8     // batches per attn block
#define ABG  (32 / AB)

// ---------------- scratch ----------------
__device__ __nv_bfloat16 g_Qb[BWIN * NH * NT * HD];
__device__ __nv_bfloat16 g_Kb[BWIN * NH * NT * HD];
__device__ __nv_bfloat16 g_Vb[BWIN * NH * NT * HD];
__device__ __nv_bfloat16 g_Ob[BWIN * NT * CC];
__device__ float g_xmid[TOK * CC];
__device__ __nv_bfloat16 g_h_bf[TOK * C4];
__device__ __nv_bfloat16 g_wqkv[CC * C3];
__device__ __nv_bfloat16 g_wproj[CC * CC];
__device__ __nv_bfloat16 g_wfc1[CC * C4];
__device__ __nv_bfloat16 g_wfc2[C4 * CC];
__device__ __nv_bfloat16 g_bias_mask[64 * NH * NT * NT];   // [w][head][i][j]

// ---------------- asm helpers ----------------
__device__ __forceinline__ void ldsm_x4(uint32_t (&r)[4], uint32_t addr) {
    asm volatile("ldmatrix.sync.aligned.m8n8.x4.shared.b16 {%0,%1,%2,%3},[%4];"
                 : "=r"(r[0]), "=r"(r[1]), "=r"(r[2]), "=r"(r[3]) : "r"(addr));
}
__device__ __forceinline__ void ldsm_x4t(uint32_t (&r)[4], uint32_t addr) {
    asm volatile("ldmatrix.sync.aligned.m8n8.x4.trans.shared.b16 {%0,%1,%2,%3},[%4];"
                 : "=r"(r[0]), "=r"(r[1]), "=r"(r[2]), "=r"(r[3]) : "r"(addr));
}
__device__ __forceinline__ void mma_bf16(float (&c)[4], const uint32_t (&a)[4],
                                         uint32_t b0, uint32_t b1) {
    asm volatile("mma.sync.aligned.m16n8k16.row.col.f32.bf16.bf16.f32 "
                 "{%0,%1,%2,%3},{%4,%5,%6,%7},{%8,%9},{%0,%1,%2,%3};"
                 : "+f"(c[0]), "+f"(c[1]), "+f"(c[2]), "+f"(c[3])
                 : "r"(a[0]), "r"(a[1]), "r"(a[2]), "r"(a[3]), "r"(b0), "r"(b1));
}
__device__ __forceinline__ void cp16(uint32_t dst, const void* src) {
    asm volatile("cp.async.cg.shared.global [%0],[%1],16;" :: "r"(dst), "l"(src));
}
#define CP_COMMIT asm volatile("cp.async.commit_group;")
#define CP_WAIT0  asm volatile("cp.async.wait_group 0;")

// ===== 128Mx64N, 8 warps as 4Mx2N, warp tile 32x32, K=192 =====
template<int PBn>
__device__ __forceinline__ void gemm128(uint32_t as_b, uint32_t bs_b,
                                        int warp, int lane, float (&acc)[2][4][4]) {
    int wm = warp >> 1, wn = warp & 1;
    uint32_t a0 = as_b + ((wm * 32 + (lane & 15)) * PA + (lane >> 4) * 8) * 2;
    int brow = (lane & 7) + ((lane >> 3) & 1) * 8;
    int bcol = (lane >> 4) * 8;
    #pragma unroll
    for (int ks = 0; ks < 12; ++ks) {
        uint32_t a[2][4];
        ldsm_x4(a[0], a0 + ks * 32);
        ldsm_x4(a[1], a0 + 16 * PA * 2 + ks * 32);
        #pragma unroll
        for (int h = 0; h < 2; ++h) {
            uint32_t b[4];
            ldsm_x4t(b, bs_b + ((ks * 16 + brow) * PBn + wn * 32 + h * 16 + bcol) * 2);
            #pragma unroll
            for (int mf = 0; mf < 2; ++mf) {
                mma_bf16(acc[mf][h * 2],     a[mf], b[0], b[1]);
                mma_bf16(acc[mf][h * 2 + 1], a[mf], b[2], b[3]);
            }
        }
    }
}

// ===== fc2 chunk: 64Mx192N x K=64, 8 warps as 2Mx4N, warp tile 32x48 =====
__device__ __forceinline__ void gemm_fc2(uint32_t as_b, uint32_t bs_b,
                                         int warp, int lane, float (&acc)[2][6][4]) {
    int wm = warp >> 2, wn = warp & 3;
    uint32_t a0 = as_b + ((wm * 32 + (lane & 15)) * PB + (lane >> 4) * 8) * 2;
    int brow = (lane & 7) + ((lane >> 3) & 1) * 8;
    int bcol = (lane >> 4) * 8;
    #pragma unroll
    for (int ks = 0; ks < 4; ++ks) {
        uint32_t a[2][4];
        ldsm_x4(a[0], a0 + ks * 32);
        ldsm_x4(a[1], a0 + 16 * PB * 2 + ks * 32);
        #pragma unroll
        for (int h = 0; h < 3; ++h) {
            uint32_t b[4];
            ldsm_x4t(b, bs_b + ((ks * 16 + brow) * PB2 + wn * 48 + h * 16 + bcol) * 2);
            #pragma unroll
            for (int mf = 0; mf < 2; ++mf) {
                mma_bf16(acc[mf][h * 2],     a[mf], b[0], b[1]);
                mma_bf16(acc[mf][h * 2 + 1], a[mf], b[2], b[3]);
            }
        }
    }
}

template<int PBn, int NCOLS>
__device__ __forceinline__ void load_b_async(const __nv_bfloat16* __restrict__ Bg,
                                             int ldg, int n0, uint32_t bs) {
    const int GPR = NCOLS / 8;
    for (int idx = threadIdx.x; idx < 192 * GPR; idx += 256) {
        int k = idx / GPR, s = idx - k * GPR;
        cp16(bs + (k * PBn + s * 8) * 2, Bg + k * ldg + n0 + s * 8);
    }
}

__device__ __forceinline__ void store_bf4(char* As, int t, int c, float4 v) {
    __nv_bfloat162 lo = __float22bfloat162_rn(make_float2(v.x, v.y));
    __nv_bfloat162 hi = __float22bfloat162_rn(make_float2(v.z, v.w));
    uint2 u;
    u.x = *reinterpret_cast<uint32_t*>(&lo);
    u.y = *reinterpret_cast<uint32_t*>(&hi);
    *reinterpret_cast<uint2*>(As + (t * PA + c) * 2) = u;
}

// ---------------- weights fp32 -> bf16 ----------------
__global__ __launch_bounds__(256) void k_cvtall(const float* __restrict__ a,
                                                const float* __restrict__ b,
                                                const float* __restrict__ c,
                                                const float* __restrict__ d)
{
    const int s0 = CC * C3, s1 = CC * CC, s2 = CC * C4, s3 = C4 * CC;
    int i = (blockIdx.x * 256 + threadIdx.x) * 4;
    if (i >= s0 + s1 + s2 + s3) return;
    const float* src; __nv_bfloat16* dst; int off;
    if (i < s0)                { src = a; dst = g_wqkv;  off = i; }
    else if (i < s0 + s1)      { src = b; dst = g_wproj; off = i - s0; }
    else if (i < s0 + s1 + s2) { src = c; dst = g_wfc1;  off = i - s0 - s1; }
    else                       { src = d; dst = g_wfc2;  off = i - s0 - s1 - s2; }
    float4 v = *(const float4*)(src + off);
    *reinterpret_cast<__nv_bfloat162*>(dst + off) =
        __float22bfloat162_rn(make_float2(v.x, v.y));
    *reinterpret_cast<__nv_bfloat162*>(dst + off + 2) =
        __float22bfloat162_rn(make_float2(v.z, v.w));
}

// ---------------- precompute bias+mask per (window, head) ----------------
__global__ __launch_bounds__(256) void k_bias(const float* __restrict__ rpb)
{
    int w = blockIdx.x / NH, head = blockIdx.x % NH;
    int wh = w >> 3, ww = w & 7;
    for (int idx = threadIdx.x; idx < NT * NT; idx += 256) {
        int i = idx >> 6, j = idx & 63;
        int dh = (i >> 3) - (j >> 3) + 7;
        int dw = (i & 7) - (j & 7) + 7;
        float v = rpb[(dh * 15 + dw) * NH + head];
        int hi = wh * 8 + (i >> 3), wi_ = ww * 8 + (i & 7);
        int hj = wh * 8 + (j >> 3), wj_ = ww * 8 + (j & 7);
        int ri = ((hi < 56) ? 0 : (hi < 60) ? 1 : 2) * 3 +
                 ((wi_ < 56) ? 0 : (wi_ < 60) ? 1 : 2);
        int rj = ((hj < 56) ? 0 : (hj < 60) ? 1 : 2) * 3 +
                 ((wj_ < 56) ? 0 : (wj_ < 60) ? 1 : 2);
        if (ri != rj) v -= 100.0f;
        g_bias_mask[(w * NH + head) * (NT * NT) + idx] = __float2bfloat16(v);
    }
}

// ================= K1: roll + window partition + QKV GEMM (2 windows/block) ==
__global__ __launch_bounds__(256) void k_qkv(const float* __restrict__ x,
                                             const float* __restrict__ bias)
{
    extern __shared__ char sm_[];
    char* As = sm_;
    uint32_t as_b = (uint32_t)__cvta_generic_to_shared(As);
    uint32_t bs0 = (uint32_t)__cvta_generic_to_shared(sm_ + 128 * PA * 2);
    uint32_t bs1 = bs0 + 192 * PB * 2;
    int wi0 = blockIdx.x * 2;
    int tid = threadIdx.x, warp = tid >> 5, lane = tid & 31;

    load_b_async<PB, 64>(g_wqkv, C3, 0, bs0);
    CP_COMMIT;

    for (int idx = tid; idx < 128 * 48; idx += 256) {
        int t = idx / 48, q = idx - t * 48;
        int wi = wi0 + (t >> 6);
        int b = wi >> 6, w = wi & 63;
        int t64 = t & 63;
        int hs = ((w >> 3) * 8 + (t64 >> 3) + SS) & 63;
        int ws = ((w & 7) * 8 + (t64 & 7) + SS) & 63;
        float4 v = *(const float4*)(x + ((b << 12) + hs * 64 + ws) * 192 + q * 4);
        store_bf4(As, t, q * 4, v);
    }

    const float qscale = 0.17677669529663687f;
    int g = lane >> 2, t2 = (lane & 3) * 2;
    int wm = warp >> 1, wn = warp & 1;
    int wi = wi0 + (wm >> 1);

    for (int nc = 0; nc < 9; ++nc) {
        CP_WAIT0;
        __syncthreads();
        if (nc < 8) {
            load_b_async<PB, 64>(g_wqkv, C3, (nc + 1) * 64, (nc & 1) ? bs0 : bs1);
            CP_COMMIT;
        }
        float acc[2][4][4] = {};
        gemm128<PB>(as_b, (nc & 1) ? bs1 : bs0, warp, lane, acc);
        #pragma unroll
        for (int nt = 0; nt < 4; ++nt) {
            int n = nc * 64 + wn * 32 + nt * 8 + t2;
            int part = n / 192, nn = n - part * 192;
            int head = nn >> 5, d = nn & 31;
            __nv_bfloat16* dst = (part == 0) ? g_Qb : (part == 1) ? g_Kb : g_Vb;
            float mul = (part == 0) ? qscale : 1.0f;
            float b0 = bias[n], b1 = bias[n + 1];
            __nv_bfloat16* base = dst + (wi * NH + head) * (NT * HD) + d;
            #pragma unroll
            for (int mf = 0; mf < 2; ++mf) {
                #pragma unroll
                for (int r = 0; r < 2; ++r) {
                    int t64 = (wm & 1) * 32 + mf * 16 + g + r * 8;
                    *reinterpret_cast<__nv_bfloat162*>(base + t64 * HD) =
                        __float22bfloat162_rn(make_float2(
                            (acc[mf][nt][r * 2]     + b0) * mul,
                            (acc[mf][nt][r * 2 + 1] + b1) * mul));
                }
            }
        }
    }
}

// ================= K2: attention, register softmax, batched =================
__global__ __launch_bounds__(256) void k_attn()
{
    __shared__ __nv_bfloat16 qs[64 * 40], ks[64 * 40], vs[64 * 40];
    __shared__ __nv_bfloat16 bias_s[64 * 64];
    __shared__ __nv_bfloat16 ps[64 * 72];
    __shared__ float smax[2][64];
    __shared__ float ssum[2][64];

    int bx = blockIdx.x;
    int whead = bx >> 2;              // 0..383 : (w, head)
    int bgrp = bx & 3;                // batch group
    int w = whead / NH, head = whead - w * NH;
    int tid = threadIdx.x, warp = tid >> 5, lane = tid & 31;
    int wm = warp >> 1, wn = warp & 1;
    int g = lane >> 2, t2 = (lane & 3) * 2;

    uint32_t qs_b = (uint32_t)__cvta_generic_to_shared(qs);
    uint32_t ks_b = (uint32_t)__cvta_generic_to_shared(ks);
    uint32_t vs_b = (uint32_t)__cvta_generic_to_shared(vs);
    uint32_t ps_b = (uint32_t)__cvta_generic_to_shared(ps);

    const __nv_bfloat16* Bp = g_bias_mask + (w * NH + head) * (NT * NT);
    for (int idx = tid; idx < 512; idx += 256)
        *reinterpret_cast<uint4*>(bias_s + idx * 8) = ((const uint4*)Bp)[idx];

    int i0 = wm * 16 + g;   // rows i0, i0+8

    for (int it = 0; it < AB; ++it) {
        int b = bgrp * AB + it;
        int wi = b * 64 + w;
        const __nv_bfloat16* Qp = g_Qb + (wi * NH + head) * (NT * HD);
        const __nv_bfloat16* Kp = g_Kb + (wi * NH + head) * (NT * HD);
        const __nv_bfloat16* Vp = g_Vb + (wi * NH + head) * (NT * HD);

        for (int idx = tid; idx < 512; idx += 256) {
            int t = idx >> 3, s = idx & 7;
            *reinterpret_cast<uint2*>(qs + t * 40 + s * 4) = ((const uint2*)Qp)[idx];
            *reinterpret_cast<uint2*>(ks + t * 40 + s * 4) = ((const uint2*)Kp)[idx];
            *reinterpret_cast<uint2*>(vs + t * 40 + s * 4) = ((const uint2*)Vp)[idx];
        }
        __syncthreads();

        float acc[4][4];

        // ---- S = Q K^T, bias added in registers ----
        {
            uint32_t qaddr = qs_b + ((wm * 16 + (lane & 15)) * 40 + (lane >> 4) * 8) * 2;
            int bn = wn * 32 + (lane >> 4) * 8 + (lane & 7);
            int ksel = ((lane >> 3) & 1) * 8;
            #pragma unroll
            for (int nt = 0; nt < 4; ++nt)
                #pragma unroll
                for (int q = 0; q < 4; ++q) acc[nt][q] = 0.f;
            #pragma unroll
            for (int ks2 = 0; ks2 < 2; ++ks2) {
                uint32_t a[4];
                ldsm_x4(a, qaddr + ks2 * 32);
                #pragma unroll
                for (int h = 0; h < 2; ++h) {
                    uint32_t bfr[4];
                    ldsm_x4(bfr, ks_b + ((bn + h * 16) * 40 + ks2 * 16 + ksel) * 2);
                    mma_bf16(acc[h * 2],     a, bfr[0], bfr[1]);
                    mma_bf16(acc[h * 2 + 1], a, bfr[2], bfr[3]);
                }
            }
            #pragma unroll
            for (int nt = 0; nt < 4; ++nt) {
                int j0 = wn * 32 + nt * 8 + t2;
                #pragma unroll
                for (int r = 0; r < 2; ++r) {
                    float2 bmf = __bfloat1622float2(
                        *reinterpret_cast<const __nv_bfloat162*>(
                            bias_s + (i0 + r * 8) * 64 + j0));
                    acc[nt][r * 2]     += bmf.x;
                    acc[nt][r * 2 + 1] += bmf.y;
                }
            }
        }

        // ---- register softmax ----
        float mx0 = -1e30f, mx1 = -1e30f;
        #pragma unroll
        for (int nt = 0; nt < 4; ++nt) {
            mx0 = fmaxf(mx0, fmaxf(acc[nt][0], acc[nt][1]));
            mx1 = fmaxf(mx1, fmaxf(acc[nt][2], acc[nt][3]));
        }
        mx0 = fmaxf(mx0, __shfl_xor_sync(~0u, mx0, 1));
        mx0 = fmaxf(mx0, __shfl_xor_sync(~0u, mx0, 2));
        mx1 = fmaxf(mx1, __shfl_xor_sync(~0u, mx1, 1));
        mx1 = fmaxf(mx1, __shfl_xor_sync(~0u, mx1, 2));
        if ((lane & 3) == 0) {
            smax[wn][i0]     = mx0;
            smax[wn][i0 + 8] = mx1;
        }
        __syncthreads();
        float fm0 = fmaxf(smax[0][i0],     smax[1][i0]);
        float fm1 = fmaxf(smax[0][i0 + 8], smax[1][i0 + 8]);

        float s0 = 0.f, s1 = 0.f;
        #pragma unroll
        for (int nt = 0; nt < 4; ++nt) {
            acc[nt][0] = __expf(acc[nt][0] - fm0);
            acc[nt][1] = __expf(acc[nt][1] - fm0);
            acc[nt][2] = __expf(acc[nt][2] - fm1);
            acc[nt][3] = __expf(acc[nt][3] - fm1);
            s0 += acc[nt][0] + acc[nt][1];
            s1 += acc[nt][2] + acc[nt][3];
        }
        s0 += __shfl_xor_sync(~0u, s0, 1);
        s0 += __shfl_xor_sync(~0u, s0, 2);
        s1 += __shfl_xor_sync(~0u, s1, 1);
        s1 += __shfl_xor_sync(~0u, s1, 2);
        if ((lane & 3) == 0) {
            ssum[wn][i0]     = s0;
            ssum[wn][i0 + 8] = s1;
        }
        __syncthreads();
        float inv0 = 1.0f / (ssum[0][i0]     + ssum[1][i0]);
        float inv1 = 1.0f / (ssum[0][i0 + 8] + ssum[1][i0 + 8]);

        // ---- P (bf16) -> ps smem ----
        #pragma unroll
        for (int nt = 0; nt < 4; ++nt) {
            int j0 = wn * 32 + nt * 8 + t2;
            *reinterpret_cast<__nv_bfloat162*>(ps + i0 * 72 + j0) =
                __float22bfloat162_rn(make_float2(acc[nt][0] * inv0, acc[nt][1] * inv0));
            *reinterpret_cast<__nv_bfloat162*>(ps + (i0 + 8) * 72 + j0) =
                __float22bfloat162_rn(make_float2(acc[nt][2] * inv1, acc[nt][3] * inv1));
        }
        __syncthreads();

        // ---- O = P V ----
        {
            uint32_t paddr = ps_b + ((wm * 16 + (lane & 15)) * 72 + (lane >> 4) * 8) * 2;
            int vrow = (lane & 7) + ((lane >> 3) & 1) * 8;
            int vcol = wn * 16 + (lane >> 4) * 8;
            float ao[2][4] = {};
            #pragma unroll
            for (int ks4 = 0; ks4 < 4; ++ks4) {
                uint32_t a[4];
                ldsm_x4(a, paddr + ks4 * 32);
                uint32_t bfr[4];
                ldsm_x4t(bfr, vs_b + ((ks4 * 16 + vrow) * 40 + vcol) * 2);
                mma_bf16(ao[0], a, bfr[0], bfr[1]);
                mma_bf16(ao[1], a, bfr[2], bfr[3]);
            }
            #pragma unroll
            for (int u = 0; u < 2; ++u) {
                int d = wn * 16 + u * 8 + t2;
                #pragma unroll
                for (int r = 0; r < 2; ++r) {
                    int i = wm * 16 + g + r * 8;
                    *reinterpret_cast<__nv_bfloat162*>(
                        g_Ob + (wi * 64 + i) * CC + head * HD + d) =
                        __float22bfloat162_rn(make_float2(ao[u][r * 2], ao[u][r * 2 + 1]));
                }
            }
        }
        __syncthreads();   // qs/ks/vs/ps reused next iteration
    }
}

// ================= K3: proj + reverse + roll + residual (2 windows/block) ====
__global__ __launch_bounds__(256) void k_proj(const float* __restrict__ x,
                                              const float* __restrict__ bias)
{
    extern __shared__ char sm_[];
    uint32_t as_b = (uint32_t)__cvta_generic_to_shared(sm_);
    uint32_t bs0 = as_b + 128 * PA * 2;
    uint32_t bs1 = bs0 + 192 * PB * 2;
    int wi0 = blockIdx.x * 2;
    int tid = threadIdx.x, warp = tid >> 5, lane = tid & 31;

    for (int idx = tid; idx < 128 * 24; idx += 256) {
        int t = idx / 24, s = idx - t * 24;
        cp16(as_b + (t * PA + s * 8) * 2, g_Ob + (wi0 * 64 + t) * CC + s * 8);
    }
    load_b_async<PB, 64>(g_wproj, CC, 0, bs0);
    CP_COMMIT;

    int g = lane >> 2, t2 = (lane & 3) * 2;
    int wm = warp >> 1, wn = warp & 1;
    int wi = wi0 + (wm >> 1);
    int b = wi >> 6, w = wi & 63, wh = w >> 3, ww = w & 7;

    for (int nc = 0; nc < 3; ++nc) {
        CP_WAIT0;
        __syncthreads();
        if (nc < 2) {
            load_b_async<PB, 64>(g_wproj, CC, (nc + 1) * 64, (nc & 1) ? bs0 : bs1);
            CP_COMMIT;
        }
        float acc[2][4][4] = {};
        gemm128<PB>(as_b, (nc & 1) ? bs1 : bs0, warp, lane, acc);
        #pragma unroll
        for (int mf = 0; mf < 2; ++mf) {
            #pragma unroll
            for (int r = 0; r < 2; ++r) {
                int t64 = (wm & 1) * 32 + mf * 16 + g + r * 8;
                int hs = (wh * 8 + (t64 >> 3) + SS) & 63;
                int ws = (ww * 8 + (t64 & 7) + SS) & 63;
                int rowbase = ((b << 12) + hs * 64 + ws) * CC;
                #pragma unroll
                for (int nt = 0; nt < 4; ++nt) {
                    int n = nc * 64 + wn * 32 + nt * 8 + t2;
                    int off = rowbase + n;
                    float2 xv = *(const float2*)(x + off);
                    float2 o;
                    o.x = xv.x + acc[mf][nt][r * 2]     + bias[n];
                    o.y = xv.y + acc[mf][nt][r * 2 + 1] + bias[n + 1];
                    *(float2*)(g_xmid + off) = o;
                }
            }
        }
    }
}

// ================= K4: fc1 + exact GELU (128 rows/block) =================
__global__ __launch_bounds__(256) void k_fc1(const float* __restrict__ bias)
{
    extern __shared__ char sm_[];
    char* As = sm_;
    uint32_t as_b = (uint32_t)__cvta_generic_to_shared(sm_);
    uint32_t bs0 = as_b + 128 * PA * 2;
    uint32_t bs1 = bs0 + 192 * PB * 2;
    int r0 = blockIdx.x * 128;
    int tid = threadIdx.x, warp = tid >> 5, lane = tid & 31;

    load_b_async<PB, 64>(g_wfc1, C4, 0, bs0);
    CP_COMMIT;

    // stage A from fp32 xmid, converting to bf16
    for (int idx = tid; idx < 128 * 48; idx += 256) {
        int t = idx / 48, q = idx - t * 48;
        float4 v = *(const float4*)(g_xmid + (r0 + t) * CC + q * 4);
        store_bf4(As, t, q * 4, v);
    }

    int g = lane >> 2, t2 = (lane & 3) * 2;
    int wm = warp >> 1, wn = warp & 1;
    const float is2 = 0.70710678118654752f;

    for (int nc = 0; nc < 12; ++nc) {
        CP_WAIT0;
        __syncthreads();
        if (nc < 11) {
            load_b_async<PB, 64>(g_wfc1, C4, (nc + 1) * 64, (nc & 1) ? bs0 : bs1);
            CP_COMMIT;
        }
        float acc[2][4][4] = {};
        gemm128<PB>(as_b, (nc & 1) ? bs1 : bs0, warp, lane, acc);
        #pragma unroll
        for (int nt = 0; nt < 4; ++nt) {
            int n = nc * 64 + wn * 32 + nt * 8 + t2;
            float b0 = bias[n], b1 = bias[n + 1];
            #pragma unroll
            for (int mf = 0; mf < 2; ++mf) {
                #pragma unroll
                for (int r = 0; r < 2; ++r) {
                    int row = wm * 32 + mf * 16 + g + r * 8;
                    float v0 = acc[mf][nt][r * 2]     + b0;
                    float v1 = acc[mf][nt][r * 2 + 1] + b1;
                    float2 o;
                    o.x = 0.5f * v0 * (1.0f + erff(v0 * is2));
                    o.y = 0.5f * v1 * (1.0f + erff(v1 * is2));
                    *reinterpret_cast<__nv_bfloat162*>(
                        g_h_bf + (r0 + row) * C4 + n) = __float22bfloat162_rn(o);
                }
            }
        }
    }
}

// ================= K5: fc2 K-chunked + residual -> out =================
__global__ __launch_bounds__(256) void k_fc2(const float* __restrict__ bias,
                                             float* __restrict__ out)
{
    extern __shared__ char sm_[];
    const int ASZ = 64 * PB * 2;
    const int BSZ = 64 * PB2 * 2;
    uint32_t as0 = (uint32_t)__cvta_generic_to_shared(sm_);
    uint32_t as1 = as0 + ASZ;
    uint32_t bs0 = as0 + 2 * ASZ;
    uint32_t bs1 = bs0 + BSZ;
    int r0 = blockIdx.x * 64;
    int tid = threadIdx.x, warp = tid >> 5, lane = tid & 31;

    for (int idx = tid; idx < 512; idx += 256) {
        int t = idx >> 3, s = idx & 7;
        cp16(as0 + (t * PB + s * 8) * 2, g_h_bf + (r0 + t) * C4 + s * 8);
    }
    for (int idx = tid; idx < 64 * 24; idx += 256) {
        int k = idx / 24, s = idx - k * 24;
        cp16(bs0 + (k * PB2 + s * 8) * 2, g_wfc2 + k * CC + s * 8);
    }
    CP_COMMIT;

    float acc[2][6][4] = {};

    for (int kc = 0; kc < 12; ++kc) {
        CP_WAIT0;
        __syncthreads();
        if (kc < 11) {
            uint32_t asn = ((kc + 1) & 1) ? as1 : as0;
            uint32_t bsn = ((kc + 1) & 1) ? bs1 : bs0;
            int k0 = (kc + 1) * 64;
            for (int idx = tid; idx < 512; idx += 256) {
                int t = idx >> 3, s = idx & 7;
                cp16(asn + (t * PB + s * 8) * 2, g_h_bf + (r0 + t) * C4 + k0 + s * 8);
            }
            for (int idx = tid; idx < 64 * 24; idx += 256) {
                int k = idx / 24, s = idx - k * 24;
                cp16(bsn + (k * PB2 + s * 8) * 2, g_wfc2 + (k0 + k) * CC + s * 8);
            }
            CP_COMMIT;
        }
        gemm_fc2((kc & 1) ? as1 : as0, (kc & 1) ? bs1 : bs0, warp, lane, acc);
    }

    int g = lane >> 2, t2 = (lane & 3) * 2;
    int wm = warp >> 2, wn = warp & 3;
    #pragma unroll
    for (int nt = 0; nt < 6; ++nt) {
        int n = wn * 48 + nt * 8 + t2;
        float b0 = bias[n], b1 = bias[n + 1];
        #pragma unroll
        for (int mf = 0; mf < 2; ++mf) {
            #pragma unroll
            for (int r = 0; r < 2; ++r) {
                int row = wm * 32 + mf * 16 + g + r * 8;
                int off = (r0 + row) * CC + n;
                float2 xv = *(const float2*)(g_xmid + off);
                float2 o;
                o.x = xv.x + acc[mf][nt][r * 2]     + b0;
                o.y = xv.y + acc[mf][nt][r * 2 + 1] + b1;
                *(float2*)(out + off) = o;
            }
        }
    }
}

// ================= launch =================
extern "C" void kernel_launch(void* const* d_in, const int* in_sizes, int n_in,
                              void* d_out, int out_size)
{
    const float* x      = (const float*)d_in[0];
    const float* rpb    = (const float*)d_in[1];
    const float* qkv_w  = (const float*)d_in[2];
    const float* qkv_b  = (const float*)d_in[3];
    const float* proj_w = (const float*)d_in[4];
    const float* proj_b = (const float*)d_in[5];
    const float* fc1_w  = (const float*)d_in[6];
    const float* fc1_b  = (const float*)d_in[7];
    const float* fc2_w  = (const float*)d_in[8];
    const float* fc2_b  = (const float*)d_in[9];
    float* out = (float*)d_out;

    const int SM_STD = 128 * PA * 2 + 2 * 192 * PB * 2;           // 106496
    const int SM_FC2 = 2 * 64 * PB * 2 + 2 * 64 * PB2 * 2;        // 69632
    cudaFuncSetAttribute(k_qkv,  cudaFuncAttributeMaxDynamicSharedMemorySize, SM_STD);
    cudaFuncSetAttribute(k_proj, cudaFuncAttributeMaxDynamicSharedMemorySize, SM_STD);
    cudaFuncSetAttribute(k_fc1,  cudaFuncAttributeMaxDynamicSharedMemorySize, SM_STD);
    cudaFuncSetAttribute(k_fc2,  cudaFuncAttributeMaxDynamicSharedMemorySize, SM_FC2);

    const int tot = CC * C3 + CC * CC + CC * C4 + C4 * CC;
    k_cvtall<<<(tot / 4 + 255) / 256, 256>>>(qkv_w, proj_w, fc1_w, fc2_w);
    k_bias<<<64 * NH, 256>>>(rpb);

    k_qkv <<<BWIN / 2, 256, SM_STD>>>(x, qkv_b);
    k_attn<<<64 * NH * ABG, 256>>>();
    k_proj<<<BWIN / 2, 256, SM_STD>>>(x, proj_b);
    k_fc1 <<<TOK / 128, 256, SM_STD>>>(fc1_b);
    k_fc2 <<<TOK / 64, 256, SM_FC2>>>(fc2_b, out);
}

// round 17
// speedup vs baseline: 1.0189x; 1.0189x over previous
#include <cuda_runtime.h>
#include <cuda_bf16.h>
#include <math.h>
#include <stdint.h>

// ---------------- problem constants ----------------
#define CC   192
#define SS   4
#define NH   6
#define HD   32
#define NT   64
#define BWIN 2048
#define TOK  131072
#define C3   576
#define C4   768

#define PA   200   // A smem pitch (bf16 elems)
#define PB   72    // pitch for 64-col chunks
#define PB2  200   // pitch for 192-col chunks (fc2 B)

// ---------------- scratch ----------------
__device__ __nv_bfloat16 g_Qb[BWIN * NH * NT * HD];
__device__ __nv_bfloat16 g_Kb[BWIN * NH * NT * HD];
__device__ __nv_bfloat16 g_Vb[BWIN * NH * NT * HD];
__device__ __nv_bfloat16 g_Ob[BWIN * NT * CC];
__device__ float g_xmid[TOK * CC];
__device__ __nv_bfloat16 g_h_bf[TOK * C4];
__device__ __nv_bfloat16 g_wqkv[CC * C3];
__device__ __nv_bfloat16 g_wproj[CC * CC];
__device__ __nv_bfloat16 g_wfc1[CC * C4];
__device__ __nv_bfloat16 g_wfc2[C4 * CC];
__device__ __nv_bfloat16 g_bias_mask[64 * NH * NT * NT];   // [w][head][i][j]

// ---------------- asm helpers ----------------
__device__ __forceinline__ void ldsm_x4(uint32_t (&r)[4], uint32_t addr) {
    asm volatile("ldmatrix.sync.aligned.m8n8.x4.shared.b16 {%0,%1,%2,%3},[%4];"
                 : "=r"(r[0]), "=r"(r[1]), "=r"(r[2]), "=r"(r[3]) : "r"(addr));
}
__device__ __forceinline__ void ldsm_x4t(uint32_t (&r)[4], uint32_t addr) {
    asm volatile("ldmatrix.sync.aligned.m8n8.x4.trans.shared.b16 {%0,%1,%2,%3},[%4];"
                 : "=r"(r[0]), "=r"(r[1]), "=r"(r[2]), "=r"(r[3]) : "r"(addr));
}
__device__ __forceinline__ void mma_bf16(float (&c)[4], const uint32_t (&a)[4],
                                         uint32_t b0, uint32_t b1) {
    asm volatile("mma.sync.aligned.m16n8k16.row.col.f32.bf16.bf16.f32 "
                 "{%0,%1,%2,%3},{%4,%5,%6,%7},{%8,%9},{%0,%1,%2,%3};"
                 : "+f"(c[0]), "+f"(c[1]), "+f"(c[2]), "+f"(c[3])
                 : "r"(a[0]), "r"(a[1]), "r"(a[2]), "r"(a[3]), "r"(b0), "r"(b1));
}
__device__ __forceinline__ void cp16(uint32_t dst, const void* src) {
    asm volatile("cp.async.cg.shared.global [%0],[%1],16;" :: "r"(dst), "l"(src));
}
#define CP_COMMIT asm volatile("cp.async.commit_group;")
#define CP_WAIT0  asm volatile("cp.async.wait_group 0;")

// ===== 128Mx64N, 8 warps as 4Mx2N, warp tile 32x32, K=192 =====
template<int PBn>
__device__ __forceinline__ void gemm128(uint32_t as_b, uint32_t bs_b,
                                        int warp, int lane, float (&acc)[2][4][4]) {
    int wm = warp >> 1, wn = warp & 1;
    uint32_t a0 = as_b + ((wm * 32 + (lane & 15)) * PA + (lane >> 4) * 8) * 2;
    int brow = (lane & 7) + ((lane >> 3) & 1) * 8;
    int bcol = (lane >> 4) * 8;
    #pragma unroll
    for (int ks = 0; ks < 12; ++ks) {
        uint32_t a[2][4];
        ldsm_x4(a[0], a0 + ks * 32);
        ldsm_x4(a[1], a0 + 16 * PA * 2 + ks * 32);
        #pragma unroll
        for (int h = 0; h < 2; ++h) {
            uint32_t b[4];
            ldsm_x4t(b, bs_b + ((ks * 16 + brow) * PBn + wn * 32 + h * 16 + bcol) * 2);
            #pragma unroll
            for (int mf = 0; mf < 2; ++mf) {
                mma_bf16(acc[mf][h * 2],     a[mf], b[0], b[1]);
                mma_bf16(acc[mf][h * 2 + 1], a[mf], b[2], b[3]);
            }
        }
    }
}

// ===== fc2 chunk: 64Mx192N x K=64, 8 warps as 2Mx4N, warp tile 32x48 =====
__device__ __forceinline__ void gemm_fc2(uint32_t as_b, uint32_t bs_b,
                                         int warp, int lane, float (&acc)[2][6][4]) {
    int wm = warp >> 2, wn = warp & 3;
    uint32_t a0 = as_b + ((wm * 32 + (lane & 15)) * PB + (lane >> 4) * 8) * 2;
    int brow = (lane & 7) + ((lane >> 3) & 1) * 8;
    int bcol = (lane >> 4) * 8;
    #pragma unroll
    for (int ks = 0; ks < 4; ++ks) {
        uint32_t a[2][4];
        ldsm_x4(a[0], a0 + ks * 32);
        ldsm_x4(a[1], a0 + 16 * PB * 2 + ks * 32);
        #pragma unroll
        for (int h = 0; h < 3; ++h) {
            uint32_t b[4];
            ldsm_x4t(b, bs_b + ((ks * 16 + brow) * PB2 + wn * 48 + h * 16 + bcol) * 2);
            #pragma unroll
            for (int mf = 0; mf < 2; ++mf) {
                mma_bf16(acc[mf][h * 2],     a[mf], b[0], b[1]);
                mma_bf16(acc[mf][h * 2 + 1], a[mf], b[2], b[3]);
            }
        }
    }
}

template<int PBn, int NCOLS>
__device__ __forceinline__ void load_b_async(const __nv_bfloat16* __restrict__ Bg,
                                             int ldg, int n0, uint32_t bs) {
    const int GPR = NCOLS / 8;
    for (int idx = threadIdx.x; idx < 192 * GPR; idx += 256) {
        int k = idx / GPR, s = idx - k * GPR;
        cp16(bs + (k * PBn + s * 8) * 2, Bg + k * ldg + n0 + s * 8);
    }
}

__device__ __forceinline__ void store_bf4(char* As, int t, int c, float4 v) {
    __nv_bfloat162 lo = __float22bfloat162_rn(make_float2(v.x, v.y));
    __nv_bfloat162 hi = __float22bfloat162_rn(make_float2(v.z, v.w));
    uint2 u;
    u.x = *reinterpret_cast<uint32_t*>(&lo);
    u.y = *reinterpret_cast<uint32_t*>(&hi);
    *reinterpret_cast<uint2*>(As + (t * PA + c) * 2) = u;
}

// ---------------- weights fp32 -> bf16 ----------------
__global__ __launch_bounds__(256) void k_cvtall(const float* __restrict__ a,
                                                const float* __restrict__ b,
                                                const float* __restrict__ c,
                                                const float* __restrict__ d)
{
    const int s0 = CC * C3, s1 = CC * CC, s2 = CC * C4, s3 = C4 * CC;
    int i = (blockIdx.x * 256 + threadIdx.x) * 4;
    if (i >= s0 + s1 + s2 + s3) return;
    const float* src; __nv_bfloat16* dst; int off;
    if (i < s0)                { src = a; dst = g_wqkv;  off = i; }
    else if (i < s0 + s1)      { src = b; dst = g_wproj; off = i - s0; }
    else if (i < s0 + s1 + s2) { src = c; dst = g_wfc1;  off = i - s0 - s1; }
    else                       { src = d; dst = g_wfc2;  off = i - s0 - s1 - s2; }
    float4 v = *(const float4*)(src + off);
    *reinterpret_cast<__nv_bfloat162*>(dst + off) =
        __float22bfloat162_rn(make_float2(v.x, v.y));
    *reinterpret_cast<__nv_bfloat162*>(dst + off + 2) =
        __float22bfloat162_rn(make_float2(v.z, v.w));
}

// ---------------- precompute bias+mask per (window, head) ----------------
__global__ __launch_bounds__(256) void k_bias(const float* __restrict__ rpb)
{
    int w = blockIdx.x / NH, head = blockIdx.x % NH;
    int wh = w >> 3, ww = w & 7;
    for (int idx = threadIdx.x; idx < NT * NT; idx += 256) {
        int i = idx >> 6, j = idx & 63;
        int dh = (i >> 3) - (j >> 3) + 7;
        int dw = (i & 7) - (j & 7) + 7;
        float v = rpb[(dh * 15 + dw) * NH + head];
        int hi = wh * 8 + (i >> 3), wi_ = ww * 8 + (i & 7);
        int hj = wh * 8 + (j >> 3), wj_ = ww * 8 + (j & 7);
        int ri = ((hi < 56) ? 0 : (hi < 60) ? 1 : 2) * 3 +
                 ((wi_ < 56) ? 0 : (wi_ < 60) ? 1 : 2);
        int rj = ((hj < 56) ? 0 : (hj < 60) ? 1 : 2) * 3 +
                 ((wj_ < 56) ? 0 : (wj_ < 60) ? 1 : 2);
        if (ri != rj) v -= 100.0f;
        g_bias_mask[(w * NH + head) * (NT * NT) + idx] = __float2bfloat16(v);
    }
}

// ================= K1: roll + window partition + QKV GEMM (2 windows/block) ==
__global__ __launch_bounds__(256) void k_qkv(const float* __restrict__ x,
                                             const float* __restrict__ bias)
{
    extern __shared__ char sm_[];
    char* As = sm_;
    uint32_t as_b = (uint32_t)__cvta_generic_to_shared(As);
    uint32_t bs0 = (uint32_t)__cvta_generic_to_shared(sm_ + 128 * PA * 2);
    uint32_t bs1 = bs0 + 192 * PB * 2;
    int wi0 = blockIdx.x * 2;
    int tid = threadIdx.x, warp = tid >> 5, lane = tid & 31;

    load_b_async<PB, 64>(g_wqkv, C3, 0, bs0);
    CP_COMMIT;

    for (int idx = tid; idx < 128 * 48; idx += 256) {
        int t = idx / 48, q = idx - t * 48;
        int wi = wi0 + (t >> 6);
        int b = wi >> 6, w = wi & 63;
        int t64 = t & 63;
        int hs = ((w >> 3) * 8 + (t64 >> 3) + SS) & 63;
        int ws = ((w & 7) * 8 + (t64 & 7) + SS) & 63;
        float4 v = *(const float4*)(x + ((b << 12) + hs * 64 + ws) * 192 + q * 4);
        store_bf4(As, t, q * 4, v);
    }

    const float qscale = 0.17677669529663687f;
    int g = lane >> 2, t2 = (lane & 3) * 2;
    int wm = warp >> 1, wn = warp & 1;
    int wi = wi0 + (wm >> 1);

    for (int nc = 0; nc < 9; ++nc) {
        CP_WAIT0;
        __syncthreads();
        if (nc < 8) {
            load_b_async<PB, 64>(g_wqkv, C3, (nc + 1) * 64, (nc & 1) ? bs0 : bs1);
            CP_COMMIT;
        }
        float acc[2][4][4] = {};
        gemm128<PB>(as_b, (nc & 1) ? bs1 : bs0, warp, lane, acc);
        #pragma unroll
        for (int nt = 0; nt < 4; ++nt) {
            int n = nc * 64 + wn * 32 + nt * 8 + t2;
            int part = n / 192, nn = n - part * 192;
            int head = nn >> 5, d = nn & 31;
            __nv_bfloat16* dst = (part == 0) ? g_Qb : (part == 1) ? g_Kb : g_Vb;
            float mul = (part == 0) ? qscale : 1.0f;
            float b0 = bias[n], b1 = bias[n + 1];
            __nv_bfloat16* base = dst + (wi * NH + head) * (NT * HD) + d;
            #pragma unroll
            for (int mf = 0; mf < 2; ++mf) {
                #pragma unroll
                for (int r = 0; r < 2; ++r) {
                    int t64 = (wm & 1) * 32 + mf * 16 + g + r * 8;
                    *reinterpret_cast<__nv_bfloat162*>(base + t64 * HD) =
                        __float22bfloat162_rn(make_float2(
                            (acc[mf][nt][r * 2]     + b0) * mul,
                            (acc[mf][nt][r * 2 + 1] + b1) * mul));
                }
            }
        }
    }
}

// ================= K2: attention, register softmax (no max pass) ============
__global__ __launch_bounds__(256) void k_attn()
{
    __shared__ __nv_bfloat16 qs[64 * 40], ks[64 * 40], vs[64 * 40];
    __shared__ char ps_raw[64 * 72 * 2];   // aliased: bias slice, then P (bf16)
    __shared__ float ssum[2][64];

    __nv_bfloat16* bias_s = reinterpret_cast<__nv_bfloat16*>(ps_raw);
    __nv_bfloat16* ps = reinterpret_cast<__nv_bfloat16*>(ps_raw);

    int bx = blockIdx.x;
    int wi = bx / NH, head = bx - wi * NH;
    int tid = threadIdx.x, warp = tid >> 5, lane = tid & 31;
    int wm = warp >> 1, wn = warp & 1;
    int g = lane >> 2, t2 = (lane & 3) * 2;

    uint32_t qs_b = (uint32_t)__cvta_generic_to_shared(qs);
    uint32_t ks_b = (uint32_t)__cvta_generic_to_shared(ks);
    uint32_t vs_b = (uint32_t)__cvta_generic_to_shared(vs);
    uint32_t ps_b = (uint32_t)__cvta_generic_to_shared(ps_raw);

    const __nv_bfloat16* Qp = g_Qb + (wi * NH + head) * (NT * HD);
    const __nv_bfloat16* Kp = g_Kb + (wi * NH + head) * (NT * HD);
    const __nv_bfloat16* Vp = g_Vb + (wi * NH + head) * (NT * HD);
    const __nv_bfloat16* Bp = g_bias_mask + ((wi & 63) * NH + head) * (NT * NT);

    for (int idx = tid; idx < 512; idx += 256) {
        int t = idx >> 3, s = idx & 7;
        *reinterpret_cast<uint2*>(qs + t * 40 + s * 4) = ((const uint2*)Qp)[idx];
        *reinterpret_cast<uint2*>(ks + t * 40 + s * 4) = ((const uint2*)Kp)[idx];
        *reinterpret_cast<uint2*>(vs + t * 40 + s * 4) = ((const uint2*)Vp)[idx];
        *reinterpret_cast<uint4*>(bias_s + idx * 8) = ((const uint4*)Bp)[idx];
    }
    __syncthreads();

    int i0 = wm * 16 + g;   // rows i0, i0+8
    float acc[4][4];

    // ---- S = Q K^T, bias added in registers ----
    {
        uint32_t qaddr = qs_b + ((wm * 16 + (lane & 15)) * 40 + (lane >> 4) * 8) * 2;
        int bn = wn * 32 + (lane >> 4) * 8 + (lane & 7);
        int ksel = ((lane >> 3) & 1) * 8;
        #pragma unroll
        for (int nt = 0; nt < 4; ++nt)
            #pragma unroll
            for (int q = 0; q < 4; ++q) acc[nt][q] = 0.f;
        #pragma unroll
        for (int ks2 = 0; ks2 < 2; ++ks2) {
            uint32_t a[4];
            ldsm_x4(a, qaddr + ks2 * 32);
            #pragma unroll
            for (int h = 0; h < 2; ++h) {
                uint32_t bfr[4];
                ldsm_x4(bfr, ks_b + ((bn + h * 16) * 40 + ks2 * 16 + ksel) * 2);
                mma_bf16(acc[h * 2],     a, bfr[0], bfr[1]);
                mma_bf16(acc[h * 2 + 1], a, bfr[2], bfr[3]);
            }
        }
        #pragma unroll
        for (int nt = 0; nt < 4; ++nt) {
            int j0 = wn * 32 + nt * 8 + t2;
            #pragma unroll
            for (int r = 0; r < 2; ++r) {
                float2 bmf = __bfloat1622float2(
                    *reinterpret_cast<const __nv_bfloat162*>(
                        bias_s + (i0 + r * 8) * 64 + j0));
                acc[nt][r * 2]     += bmf.x;
                acc[nt][r * 2 + 1] += bmf.y;
            }
        }
    }

    // ---- softmax without max pass (logits bounded; masked -> exp ~ 0) ----
    float s0 = 0.f, s1 = 0.f;
    #pragma unroll
    for (int nt = 0; nt < 4; ++nt) {
        acc[nt][0] = __expf(acc[nt][0]);
        acc[nt][1] = __expf(acc[nt][1]);
        acc[nt][2] = __expf(acc[nt][2]);
        acc[nt][3] = __expf(acc[nt][3]);
        s0 += acc[nt][0] + acc[nt][1];
        s1 += acc[nt][2] + acc[nt][3];
    }
    s0 += __shfl_xor_sync(~0u, s0, 1);
    s0 += __shfl_xor_sync(~0u, s0, 2);
    s1 += __shfl_xor_sync(~0u, s1, 1);
    s1 += __shfl_xor_sync(~0u, s1, 2);
    if ((lane & 3) == 0) {
        ssum[wn][i0]     = s0;
        ssum[wn][i0 + 8] = s1;
    }
    __syncthreads();
    float inv0 = 1.0f / (ssum[0][i0]     + ssum[1][i0]);
    float inv1 = 1.0f / (ssum[0][i0 + 8] + ssum[1][i0 + 8]);

    // ---- P (bf16) -> ps smem (overwrites bias slice; reads done) ----
    #pragma unroll
    for (int nt = 0; nt < 4; ++nt) {
        int j0 = wn * 32 + nt * 8 + t2;
        *reinterpret_cast<__nv_bfloat162*>(ps + i0 * 72 + j0) =
            __float22bfloat162_rn(make_float2(acc[nt][0] * inv0, acc[nt][1] * inv0));
        *reinterpret_cast<__nv_bfloat162*>(ps + (i0 + 8) * 72 + j0) =
            __float22bfloat162_rn(make_float2(acc[nt][2] * inv1, acc[nt][3] * inv1));
    }
    __syncthreads();

    // ---- O = P V ----
    {
        uint32_t paddr = ps_b + ((wm * 16 + (lane & 15)) * 72 + (lane >> 4) * 8) * 2;
        int vrow = (lane & 7) + ((lane >> 3) & 1) * 8;
        int vcol = wn * 16 + (lane >> 4) * 8;
        float ao[2][4] = {};
        #pragma unroll
        for (int ks4 = 0; ks4 < 4; ++ks4) {
            uint32_t a[4];
            ldsm_x4(a, paddr + ks4 * 32);
            uint32_t bfr[4];
            ldsm_x4t(bfr, vs_b + ((ks4 * 16 + vrow) * 40 + vcol) * 2);
            mma_bf16(ao[0], a, bfr[0], bfr[1]);
            mma_bf16(ao[1], a, bfr[2], bfr[3]);
        }
        #pragma unroll
        for (int u = 0; u < 2; ++u) {
            int d = wn * 16 + u * 8 + t2;
            #pragma unroll
            for (int r = 0; r < 2; ++r) {
                int i = wm * 16 + g + r * 8;
                *reinterpret_cast<__nv_bfloat162*>(
                    g_Ob + (wi * 64 + i) * CC + head * HD + d) =
                    __float22bfloat162_rn(make_float2(ao[u][r * 2], ao[u][r * 2 + 1]));
            }
        }
    }
}

// ================= K3: proj + reverse + roll + residual (2 windows/block) ====
__global__ __launch_bounds__(256) void k_proj(const float* __restrict__ x,
                                              const float* __restrict__ bias)
{
    extern __shared__ char sm_[];
    uint32_t as_b = (uint32_t)__cvta_generic_to_shared(sm_);
    uint32_t bs0 = as_b + 128 * PA * 2;
    uint32_t bs1 = bs0 + 192 * PB * 2;
    int wi0 = blockIdx.x * 2;
    int tid = threadIdx.x, warp = tid >> 5, lane = tid & 31;

    for (int idx = tid; idx < 128 * 24; idx += 256) {
        int t = idx / 24, s = idx - t * 24;
        cp16(as_b + (t * PA + s * 8) * 2, g_Ob + (wi0 * 64 + t) * CC + s * 8);
    }
    load_b_async<PB, 64>(g_wproj, CC, 0, bs0);
    CP_COMMIT;

    int g = lane >> 2, t2 = (lane & 3) * 2;
    int wm = warp >> 1, wn = warp & 1;
    int wi = wi0 + (wm >> 1);
    int b = wi >> 6, w = wi & 63, wh = w >> 3, ww = w & 7;

    for (int nc = 0; nc < 3; ++nc) {
        CP_WAIT0;
        __syncthreads();
        if (nc < 2) {
            load_b_async<PB, 64>(g_wproj, CC, (nc + 1) * 64, (nc & 1) ? bs0 : bs1);
            CP_COMMIT;
        }
        float acc[2][4][4] = {};
        gemm128<PB>(as_b, (nc & 1) ? bs1 : bs0, warp, lane, acc);
        #pragma unroll
        for (int mf = 0; mf < 2; ++mf) {
            #pragma unroll
            for (int r = 0; r < 2; ++r) {
                int t64 = (wm & 1) * 32 + mf * 16 + g + r * 8;
                int hs = (wh * 8 + (t64 >> 3) + SS) & 63;
                int ws = (ww * 8 + (t64 & 7) + SS) & 63;
                int rowbase = ((b << 12) + hs * 64 + ws) * CC;
                #pragma unroll
                for (int nt = 0; nt < 4; ++nt) {
                    int n = nc * 64 + wn * 32 + nt * 8 + t2;
                    int off = rowbase + n;
                    float2 xv = *(const float2*)(x + off);
                    float2 o;
                    o.x = xv.x + acc[mf][nt][r * 2]     + bias[n];
                    o.y = xv.y + acc[mf][nt][r * 2 + 1] + bias[n + 1];
                    *(float2*)(g_xmid + off) = o;
                }
            }
        }
    }
}

// ================= K4: fc1 + exact GELU (128 rows/block) =================
__global__ __launch_bounds__(256) void k_fc1(const float* __restrict__ bias)
{
    extern __shared__ char sm_[];
    char* As = sm_;
    uint32_t as_b = (uint32_t)__cvta_generic_to_shared(sm_);
    uint32_t bs0 = as_b + 128 * PA * 2;
    uint32_t bs1 = bs0 + 192 * PB * 2;
    int r0 = blockIdx.x * 128;
    int tid = threadIdx.x, warp = tid >> 5, lane = tid & 31;

    load_b_async<PB, 64>(g_wfc1, C4, 0, bs0);
    CP_COMMIT;

    for (int idx = tid; idx < 128 * 48; idx += 256) {
        int t = idx / 48, q = idx - t * 48;
        float4 v = *(const float4*)(g_xmid + (r0 + t) * CC + q * 4);
        store_bf4(As, t, q * 4, v);
    }

    int g = lane >> 2, t2 = (lane & 3) * 2;
    int wm = warp >> 1, wn = warp & 1;
    const float is2 = 0.70710678118654752f;

    for (int nc = 0; nc < 12; ++nc) {
        CP_WAIT0;
        __syncthreads();
        if (nc < 11) {
            load_b_async<PB, 64>(g_wfc1, C4, (nc + 1) * 64, (nc & 1) ? bs0 : bs1);
            CP_COMMIT;
        }
        float acc[2][4][4] = {};
        gemm128<PB>(as_b, (nc & 1) ? bs1 : bs0, warp, lane, acc);
        #pragma unroll
        for (int nt = 0; nt < 4; ++nt) {
            int n = nc * 64 + wn * 32 + nt * 8 + t2;
            float b0 = bias[n], b1 = bias[n + 1];
            #pragma unroll
            for (int mf = 0; mf < 2; ++mf) {
                #pragma unroll
                for (int r = 0; r < 2; ++r) {
                    int row = wm * 32 + mf * 16 + g + r * 8;
                    float v0 = acc[mf][nt][r * 2]     + b0;
                    float v1 = acc[mf][nt][r * 2 + 1] + b1;
                    float2 o;
                    o.x = 0.5f * v0 * (1.0f + erff(v0 * is2));
                    o.y = 0.5f * v1 * (1.0f + erff(v1 * is2));
                    *reinterpret_cast<__nv_bfloat162*>(
                        g_h_bf + (r0 + row) * C4 + n) = __float22bfloat162_rn(o);
                }
            }
        }
    }
}

// ================= K5: fc2 K-chunked + residual -> out =================
__global__ __launch_bounds__(256) void k_fc2(const float* __restrict__ bias,
                                             float* __restrict__ out)
{
    extern __shared__ char sm_[];
    const int ASZ = 64 * PB * 2;
    const int BSZ = 64 * PB2 * 2;
    uint32_t as0 = (uint32_t)__cvta_generic_to_shared(sm_);
    uint32_t as1 = as0 + ASZ;
    uint32_t bs0 = as0 + 2 * ASZ;
    uint32_t bs1 = bs0 + BSZ;
    int r0 = blockIdx.x * 64;
    int tid = threadIdx.x, warp = tid >> 5, lane = tid & 31;

    for (int idx = tid; idx < 512; idx += 256) {
        int t = idx >> 3, s = idx & 7;
        cp16(as0 + (t * PB + s * 8) * 2, g_h_bf + (r0 + t) * C4 + s * 8);
    }
    for (int idx = tid; idx < 64 * 24; idx += 256) {
        int k = idx / 24, s = idx - k * 24;
        cp16(bs0 + (k * PB2 + s * 8) * 2, g_wfc2 + k * CC + s * 8);
    }
    CP_COMMIT;

    float acc[2][6][4] = {};

    for (int kc = 0; kc < 12; ++kc) {
        CP_WAIT0;
        __syncthreads();
        if (kc < 11) {
            uint32_t asn = ((kc + 1) & 1) ? as1 : as0;
            uint32_t bsn = ((kc + 1) & 1) ? bs1 : bs0;
            int k0 = (kc + 1) * 64;
            for (int idx = tid; idx < 512; idx += 256) {
                int t = idx >> 3, s = idx & 7;
                cp16(asn + (t * PB + s * 8) * 2, g_h_bf + (r0 + t) * C4 + k0 + s * 8);
            }
            for (int idx = tid; idx < 64 * 24; idx += 256) {
                int k = idx / 24, s = idx - k * 24;
                cp16(bsn + (k * PB2 + s * 8) * 2, g_wfc2 + (k0 + k) * CC + s * 8);
            }
            CP_COMMIT;
        }
        gemm_fc2((kc & 1) ? as1 : as0, (kc & 1) ? bs1 : bs0, warp, lane, acc);
    }

    int g = lane >> 2, t2 = (lane & 3) * 2;
    int wm = warp >> 2, wn = warp & 3;
    #pragma unroll
    for (int nt = 0; nt < 6; ++nt) {
        int n = wn * 48 + nt * 8 + t2;
        float b0 = bias[n], b1 = bias[n + 1];
        #pragma unroll
        for (int mf = 0; mf < 2; ++mf) {
            #pragma unroll
            for (int r = 0; r < 2; ++r) {
                int row = wm * 32 + mf * 16 + g + r * 8;
                int off = (r0 + row) * CC + n;
                float2 xv = *(const float2*)(g_xmid + off);
                float2 o;
                o.x = xv.x + acc[mf][nt][r * 2]     + b0;
                o.y = xv.y + acc[mf][nt][r * 2 + 1] + b1;
                *(float2*)(out + off) = o;
            }
        }
    }
}

// ================= launch =================
extern "C" void kernel_launch(void* const* d_in, const int* in_sizes, int n_in,
                              void* d_out, int out_size)
{
    const float* x      = (const float*)d_in[0];
    const float* rpb    = (const float*)d_in[1];
    const float* qkv_w  = (const float*)d_in[2];
    const float* qkv_b  = (const float*)d_in[3];
    const float* proj_w = (const float*)d_in[4];
    const float* proj_b = (const float*)d_in[5];
    const float* fc1_w  = (const float*)d_in[6];
    const float* fc1_b  = (const float*)d_in[7];
    const float* fc2_w  = (const float*)d_in[8];
    const float* fc2_b  = (const float*)d_in[9];
    float* out = (float*)d_out;

    const int SM_STD = 128 * PA * 2 + 2 * 192 * PB * 2;           // 106496
    const int SM_FC2 = 2 * 64 * PB * 2 + 2 * 64 * PB2 * 2;        // 69632
    cudaFuncSetAttribute(k_qkv,  cudaFuncAttributeMaxDynamicSharedMemorySize, SM_STD);
    cudaFuncSetAttribute(k_proj, cudaFuncAttributeMaxDynamicSharedMemorySize, SM_STD);
    cudaFuncSetAttribute(k_fc1,  cudaFuncAttributeMaxDynamicSharedMemorySize, SM_STD);
    cudaFuncSetAttribute(k_fc2,  cudaFuncAttributeMaxDynamicSharedMemorySize, SM_FC2);

    const int tot = CC * C3 + CC * CC + CC * C4 + C4 * CC;
    k_cvtall<<<(tot / 4 + 255) / 256, 256>>>(qkv_w, proj_w, fc1_w, fc2_w);
    k_bias<<<64 * NH, 256>>>(rpb);

    k_qkv <<<BWIN / 2, 256, SM_STD>>>(x, qkv_b);
    k_attn<<<BWIN * NH, 256>>>();
    k_proj<<<BWIN / 2, 256, SM_STD>>>(x, proj_b);
    k_fc1 <<<TOK / 128, 256, SM_STD>>>(fc1_b);
    k_fc2 <<<TOK / 64, 256, SM_FC2>>>(fc2_b, out);
}